// round 13
// baseline (speedup 1.0000x reference)
#include <cuda_runtime.h>
#include <math.h>

#define NPERROW (512*512)            // 262144
#define NROWS   128
#define NV4     (NPERROW/4)          // 65536
#define FULLM   0xFFFFFFFFu

// ---- gather / gate shape ----
#define CHUNKS  16
#define GTH     256
#define V4C     (NV4/CHUNKS)         // 4096 float4 per chunk
#define V4T     (V4C/GTH)            // 16 float4 per thread -> 64 elems/thread
#define GWARPS  (GTH/32)             // 8
#define TCAP    64                   // structural max elems/thread -> guard-free stores
#define CSEG    1024                 // per-chunk global segment cap (exp ~746)
#define MCAP    (CHUNKS*CSEG)        // 16384
#define GSM_BYTES (TCAP*GTH*4)       // 65536 dynamic smem for gather stage

// ---- selection ----
#define STH     1024
#define SEL_SMEM_WORDS (MCAP + 4096)              // mix + hist banks
#define SEL_SMEM_BYTES (SEL_SMEM_WORDS*4)         // 81920

__device__ unsigned int g_buf[NROWS][MCAP];    // 8 MB scratch
__device__ unsigned int g_ccnt[NROWS][CHUNKS]; // per-chunk counts (0xFFFFFFFF = overflow)
__device__ float g_q[NROWS][2];                // [0]=i1, [1]=i99

// monotone float -> uint key
__device__ __forceinline__ unsigned int f2k(float f) {
    unsigned int u = __float_as_uint(f);
    return u ^ ((unsigned int)((int)u >> 31) | 0x80000000u);
}
__device__ __forceinline__ float k2f(unsigned int k) {
    unsigned int u = (k & 0x80000000u) ? (k ^ 0x80000000u) : ~k;
    return __uint_as_float(u);
}
__device__ __forceinline__ float ex2a(float x){ float r; asm("ex2.approx.ftz.f32 %0, %1;" : "=f"(r) : "f"(x)); return r; }
__device__ __forceinline__ float rcpa(float x){ float r; asm("rcp.approx.ftz.f32 %0, %1;" : "=f"(r) : "f"(x)); return r; }

extern __shared__ unsigned int smem_u[];

// ===================== Kernel 1: wide tail gather (guard-free stage) =====================
__global__ __launch_bounds__(GTH)
void gather_kernel(const float* __restrict__ x)
{
    unsigned int* stage = smem_u;   // TCAP * GTH words (dynamic, 64 KB)
    __shared__ unsigned int wsum[GWARPS];

    const int tid  = threadIdx.x;
    const int lane = tid & 31;
    const int wid  = tid >> 5;
    const int row  = blockIdx.x >> 4;
    const int chk  = blockIdx.x & (CHUNKS - 1);
    const float4* xr = (const float4*)(x + (size_t)row * NPERROW) + (size_t)chk * V4C;

    unsigned int cnt = 0;
    #pragma unroll
    for (int it = 0; it < V4T / 8; it++) {
        float4 v[8];
        #pragma unroll
        for (int s = 0; s < 8; s++)
            v[s] = __ldcs(&xr[tid + (it * 8 + s) * GTH]);   // streaming: don't thrash L2

        #pragma unroll
        for (int s = 0; s < 8; s++) {
            if (fabsf(v[s].x) > 2.0f) { stage[cnt * GTH + tid] = f2k(v[s].x); cnt++; }
            if (fabsf(v[s].y) > 2.0f) { stage[cnt * GTH + tid] = f2k(v[s].y); cnt++; }
            if (fabsf(v[s].z) > 2.0f) { stage[cnt * GTH + tid] = f2k(v[s].z); cnt++; }
            if (fabsf(v[s].w) > 2.0f) { stage[cnt * GTH + tid] = f2k(v[s].w); cnt++; }
        }
    }
    // cnt <= 64 structurally; no per-element guard needed

    // block exclusive scan of per-thread counts
    unsigned int inc = cnt;
    #pragma unroll
    for (int o = 1; o < 32; o <<= 1) {
        unsigned int t = __shfl_up_sync(FULLM, inc, o);
        if (lane >= o) inc += t;
    }
    if (lane == 31) wsum[wid] = inc;
    __syncthreads();
    if (tid < GWARPS) {
        unsigned int w = wsum[tid];
        #pragma unroll
        for (int o = 1; o < GWARPS; o <<= 1) {
            unsigned int t = __shfl_up_sync(0xFFu, w, o);
            if (tid >= o) w += t;
        }
        wsum[tid] = w;
    }
    __syncthreads();

    unsigned int pre   = (wid ? wsum[wid - 1] : 0u) + inc - cnt;
    unsigned int total = wsum[GWARPS - 1];
    int ov = (total > CSEG);

    if (!ov) {
        unsigned int* dst = &g_buf[row][chk * CSEG + pre];
        for (unsigned int j = 0; j < cnt; j++) dst[j] = stage[j * GTH + tid];
    }
    if (tid == 0) g_ccnt[row][chk] = ov ? 0xFFFFFFFFu : total;
}

// ===================== Kernel 2: per-(row,side) radix select =====================

// block scan over h[0..bpt*1024) + locate ranks lr0/lr1.
__device__ void scan_locate2(unsigned int* h, int bpt,
                             unsigned int lr0, unsigned int lr1,
                             unsigned int* out_bin, unsigned int* out_pre,
                             unsigned int* wsum,
                             int tid, int lane, int wid)
{
    unsigned int c[2] = {0u, 0u};
    unsigned int s = 0;
    for (int j = 0; j < bpt; j++) { c[j] = h[tid * bpt + j]; s += c[j]; }
    unsigned int inc = s;
    #pragma unroll
    for (int o = 1; o < 32; o <<= 1) {
        unsigned int t = __shfl_up_sync(FULLM, inc, o);
        if (lane >= o) inc += t;
    }
    if (lane == 31) wsum[wid] = inc;
    __syncthreads();
    if (tid < 32) {
        unsigned int w = wsum[tid];
        #pragma unroll
        for (int o = 1; o < 32; o <<= 1) {
            unsigned int t = __shfl_up_sync(FULLM, w, o);
            if (lane >= o) w += t;
        }
        wsum[tid] = w;
    }
    __syncthreads();
    unsigned int run = (wid ? wsum[wid - 1] : 0u) + inc - s;
    for (int j = 0; j < bpt; j++) {
        unsigned int cc = c[j];
        if (run <= lr0 && lr0 < run + cc) { out_bin[0] = (unsigned int)(tid * bpt + j); out_pre[0] = run; }
        if (run <= lr1 && lr1 < run + cc) { out_bin[1] = (unsigned int)(tid * bpt + j); out_pre[1] = run; }
        run += cc;
    }
    __syncthreads();
}

__global__ __launch_bounds__(STH, 1)
void select_kernel(const float* __restrict__ x)
{
    unsigned int* mix = smem_u;          // MCAP
    unsigned int* h   = mix + MCAP;      // 4096 words of histogram banks

    __shared__ unsigned int wsum[32];
    __shared__ unsigned int cpre[CHUNKS + 1];
    __shared__ unsigned int s_M, s_Mside;
    __shared__ int          s_mode;
    __shared__ unsigned int bin1[2], pre1[2], bin2[2], pre2[2], bin3[2], pre3[2];

    const int tid  = threadIdx.x;
    const int lane = tid & 31;
    const int wid  = tid >> 5;
    const int row  = blockIdx.x >> 1;
    const int side = blockIdx.x & 1;
    const float4* xr = (const float4*)(x + (size_t)row * NPERROW);

    if (tid == 0) {
        unsigned int t = 0; int bad = 0;
        #pragma unroll
        for (int c = 0; c < CHUNKS; c++) {
            unsigned int cc = g_ccnt[row][c];
            if (cc > CSEG) { bad = 1; cc = 0; }
            cpre[c] = t;
            t += cc;
        }
        cpre[CHUNKS] = t;
        s_M = t;
        s_mode = bad ? 1 : 0;
        s_Mside = 0u;
    }
    __syncthreads();

    const unsigned int M = s_M;
    if (s_mode == 0) {
        unsigned int ms = 0;
        #pragma unroll
        for (int c = 0; c < CHUNKS; c++) {
            unsigned int cnt = cpre[c + 1] - cpre[c];   // <= 1024 = STH
            if ((unsigned int)tid < cnt) {
                unsigned int k = g_buf[row][c * CSEG + tid];
                mix[cpre[c] + tid] = k;
                ms += (side ? (k >= 0x80000000u) : (k < 0x80000000u));
            }
        }
        #pragma unroll
        for (int o = 16; o > 0; o >>= 1) ms += __shfl_down_sync(FULLM, ms, o);
        if (lane == 0) atomicAdd(&s_Mside, ms);
    }
    __syncthreads();

    const unsigned int Mside = s_Mside;
    if (s_mode == 0 && Mside < 2623u) { if (tid == 0) s_mode = 1; }
    __syncthreads();
    const int mode = s_mode;

    unsigned int R0, R1, key0, key1;

    if (mode == 0) {
        const unsigned int base = side ? 0xC0000000u : 0x00000000u;
        R0 = side ? (Mside - 2623u) : 2621u;
        R1 = R0 + 1u;

        // ---- pass 1: bits [20,30) of rel ----
        for (int j = tid; j < 1024; j += STH) h[j] = 0u;
        __syncthreads();
        for (unsigned int i = tid; i < M; i += STH) {
            unsigned int k = mix[i];
            if (side ? (k >= 0x80000000u) : (k < 0x80000000u))
                atomicAdd(&h[(k - base) >> 20], 1u);
        }
        __syncthreads();
        scan_locate2(h, 1, R0, R1, bin1, pre1, wsum, tid, lane, wid);

        // ---- pass 2: bits [10,20), 2 banks ----
        for (int j = tid; j < 2048; j += STH) h[j] = 0u;
        __syncthreads();
        {
            const unsigned int b0 = bin1[0], b1 = bin1[1];
            for (unsigned int i = tid; i < M; i += STH) {
                unsigned int k = mix[i];
                if (side ? (k >= 0x80000000u) : (k < 0x80000000u)) {
                    unsigned int rel = k - base;
                    unsigned int t1 = rel >> 20, sub = (rel >> 10) & 1023u;
                    if (t1 == b0) atomicAdd(&h[sub], 1u);
                    if (t1 == b1) atomicAdd(&h[1024 + sub], 1u);
                }
            }
        }
        __syncthreads();
        scan_locate2(h,        1, R0 - pre1[0], 0xFFFFFFFFu, bin2,     pre2,     wsum, tid, lane, wid);
        scan_locate2(h + 1024, 1, R1 - pre1[1], 0xFFFFFFFFu, bin2 + 1, pre2 + 1, wsum, tid, lane, wid);

        // ---- pass 3: bits [0,10), 2 banks ----
        for (int j = tid; j < 2048; j += STH) h[j] = 0u;
        __syncthreads();
        {
            const unsigned int t20_0 = (bin1[0] << 10) | bin2[0];
            const unsigned int t20_1 = (bin1[1] << 10) | bin2[1];
            for (unsigned int i = tid; i < M; i += STH) {
                unsigned int k = mix[i];
                if (side ? (k >= 0x80000000u) : (k < 0x80000000u)) {
                    unsigned int rel = k - base;
                    unsigned int t2 = rel >> 10, sub = rel & 1023u;
                    if (t2 == t20_0) atomicAdd(&h[sub], 1u);
                    if (t2 == t20_1) atomicAdd(&h[1024 + sub], 1u);
                }
            }
        }
        __syncthreads();
        scan_locate2(h,        1, R0 - pre1[0] - pre2[0], 0xFFFFFFFFu, bin3,     pre3,     wsum, tid, lane, wid);
        scan_locate2(h + 1024, 1, R1 - pre1[1] - pre2[1], 0xFFFFFFFFu, bin3 + 1, pre3 + 1, wsum, tid, lane, wid);

        key0 = base + (bin1[0] << 20) + (bin2[0] << 10) + bin3[0];
        key1 = base + (bin1[1] << 20) + (bin2[1] << 10) + bin3[1];
    } else {
        // ---- exact full-row fallback: 11/11/10-bit passes over all 32 bits ----
        R0 = side ? 259521u : 2621u;
        R1 = R0 + 1u;

        for (int j = tid; j < 2048; j += STH) h[j] = 0u;
        __syncthreads();
        for (int i = tid; i < NV4; i += STH) {
            float4 v = xr[i];
            atomicAdd(&h[f2k(v.x) >> 21], 1u);
            atomicAdd(&h[f2k(v.y) >> 21], 1u);
            atomicAdd(&h[f2k(v.z) >> 21], 1u);
            atomicAdd(&h[f2k(v.w) >> 21], 1u);
        }
        __syncthreads();
        scan_locate2(h, 2, R0, R1, bin1, pre1, wsum, tid, lane, wid);

        for (int j = tid; j < 4096; j += STH) h[j] = 0u;
        __syncthreads();
        {
            const unsigned int b0 = bin1[0], b1 = bin1[1];
            for (int i = tid; i < NV4; i += STH) {
                float4 v = xr[i];
                unsigned int ks[4] = {f2k(v.x), f2k(v.y), f2k(v.z), f2k(v.w)};
                #pragma unroll
                for (int e = 0; e < 4; e++) {
                    unsigned int t1 = ks[e] >> 21, sub = (ks[e] >> 10) & 2047u;
                    if (t1 == b0) atomicAdd(&h[sub], 1u);
                    if (t1 == b1) atomicAdd(&h[2048 + sub], 1u);
                }
            }
        }
        __syncthreads();
        scan_locate2(h,        2, R0 - pre1[0], 0xFFFFFFFFu, bin2,     pre2,     wsum, tid, lane, wid);
        scan_locate2(h + 2048, 2, R1 - pre1[1], 0xFFFFFFFFu, bin2 + 1, pre2 + 1, wsum, tid, lane, wid);

        for (int j = tid; j < 2048; j += STH) h[j] = 0u;
        __syncthreads();
        {
            const unsigned int t22_0 = (bin1[0] << 11) | bin2[0];
            const unsigned int t22_1 = (bin1[1] << 11) | bin2[1];
            for (int i = tid; i < NV4; i += STH) {
                float4 v = xr[i];
                unsigned int ks[4] = {f2k(v.x), f2k(v.y), f2k(v.z), f2k(v.w)};
                #pragma unroll
                for (int e = 0; e < 4; e++) {
                    unsigned int t2 = ks[e] >> 10, sub = ks[e] & 1023u;
                    if (t2 == t22_0) atomicAdd(&h[sub], 1u);
                    if (t2 == t22_1) atomicAdd(&h[1024 + sub], 1u);
                }
            }
        }
        __syncthreads();
        scan_locate2(h,        1, R0 - pre1[0] - pre2[0], 0xFFFFFFFFu, bin3,     pre3,     wsum, tid, lane, wid);
        scan_locate2(h + 1024, 1, R1 - pre1[1] - pre2[1], 0xFFFFFFFFu, bin3 + 1, pre3 + 1, wsum, tid, lane, wid);

        key0 = (bin1[0] << 21) | (bin2[0] << 10) | bin3[0];
        key1 = (bin1[1] << 21) | (bin2[1] << 10) | bin3[1];
    }

    if (tid == 0) {
        double frac = side ? (0.99 * (double)(NPERROW - 1) - 259521.0)
                           : (0.01 * (double)(NPERROW - 1) - 2621.0);
        double v0 = (double)k2f(key0);
        double v1 = (double)k2f(key1);
        g_q[row][side] = (float)(v0 + frac * (v1 - v0));
    }
}

// ===================== Kernel 3: streaming gate =====================
__global__ __launch_bounds__(GTH)
void gate_kernel(const float* __restrict__ x, float* __restrict__ out,
                 const float* __restrict__ alpha_p, const float* __restrict__ beta_p)
{
    const int c   = blockIdx.x;
    const int row = c >> 4;            // CHUNKS = 16
    const int chk = c & 15;
    const float4* xr   = (const float4*)(x   + (size_t)row * NPERROW) + (size_t)chk * V4C;
    float4*       outr = (float4*)      (out + (size_t)row * NPERROW) + (size_t)chk * V4C;

    // inline threshold computation (tiny, redundant per CTA)
    const double i1  = (double)g_q[row][0];
    const double i99 = (double)g_q[row][1];
    const float alpha = alpha_p[0];
    const float beta  = beta_p[0];
    const float th = (float)(i1 + (i99 - i1) * (double)alpha);
    const float mask   = (th > 1e-14f) ? 1.0f : 0.0f;
    const float th_new = th * mask + (1.0f - mask);
    const float scale  = beta / th_new;
    const float t      = th * mask;

    const float L2E = 1.4426950408889634f;
    const float a = scale * L2E;        // exp(-(scale*(|x|-t))) = 2^(-a*|x| + b)
    const float b = scale * t * L2E;

    #pragma unroll 4
    for (int i = threadIdx.x; i < V4C; i += GTH) {
        float4 v = __ldcs(&xr[i]);      // streaming loads (proven faster than L2-allocate)
        float4 o;
        o.x = fmaxf(v.x, 0.0f) * rcpa(1.0f + ex2a(fmaf(fabsf(v.x), -a, b)));
        o.y = fmaxf(v.y, 0.0f) * rcpa(1.0f + ex2a(fmaf(fabsf(v.y), -a, b)));
        o.z = fmaxf(v.z, 0.0f) * rcpa(1.0f + ex2a(fmaf(fabsf(v.z), -a, b)));
        o.w = fmaxf(v.w, 0.0f) * rcpa(1.0f + ex2a(fmaf(fabsf(v.w), -a, b)));
        __stcs(&outr[i], o);
    }
}

extern "C" void kernel_launch(void* const* d_in, const int* in_sizes, int n_in,
                              void* d_out, int out_size)
{
    const float* x     = (const float*)d_in[0];
    const float* alpha = (const float*)d_in[1];
    const float* beta  = (const float*)d_in[2];
    float* out = (float*)d_out;

    cudaFuncSetAttribute(gather_kernel, cudaFuncAttributeMaxDynamicSharedMemorySize, GSM_BYTES);
    cudaFuncSetAttribute(select_kernel, cudaFuncAttributeMaxDynamicSharedMemorySize, SEL_SMEM_BYTES);

    gather_kernel<<<NROWS * CHUNKS, GTH, GSM_BYTES>>>(x);
    select_kernel<<<NROWS * 2, STH, SEL_SMEM_BYTES>>>(x);
    gate_kernel<<<NROWS * CHUNKS, GTH>>>(x, out, alpha, beta);
}

// round 14
// speedup vs baseline: 1.1321x; 1.1321x over previous
#include <cuda_runtime.h>
#include <math.h>

#define NPERROW (512*512)            // 262144
#define NROWS   128
#define NV4     (NPERROW/4)          // 65536
#define FULLM   0xFFFFFFFFu
#define NORANK  0xFFFFFFFFu

// ---- gather / gate shape (R11-proven) ----
#define CHUNKS  16
#define GTH     256
#define V4C     (NV4/CHUNKS)         // 4096 float4 per chunk
#define V4T     (V4C/GTH)            // 16 float4 per thread
#define GWARPS  (GTH/32)             // 8
#define TCAP    24                   // per-thread stage cap
#define CSEG    1024                 // per-chunk global segment cap (exp ~746)
#define MCAP    (CHUNKS*CSEG)        // 16384

// ---- selection ----
#define STH     1024
#define CCAPS   3072                 // per-side candidate cap (exp ~1100 for 2 bins)
#define SEL_WORDS (MCAP + 8192 + 2*CCAPS)         // 30720
#define SEL_SMEM_BYTES (SEL_WORDS*4)              // 122880

__device__ unsigned int g_buf[NROWS][MCAP];    // 8 MB scratch
__device__ unsigned int g_ccnt[NROWS][CHUNKS]; // per-chunk counts (0xFFFFFFFF = overflow)
__device__ float g_q[NROWS][2];                // [0]=i1, [1]=i99

// monotone float -> uint key
__device__ __forceinline__ unsigned int f2k(float f) {
    unsigned int u = __float_as_uint(f);
    return u ^ ((unsigned int)((int)u >> 31) | 0x80000000u);
}
__device__ __forceinline__ float k2f(unsigned int k) {
    unsigned int u = (k & 0x80000000u) ? (k ^ 0x80000000u) : ~k;
    return __uint_as_float(u);
}
__device__ __forceinline__ float ex2a(float x){ float r; asm("ex2.approx.ftz.f32 %0, %1;" : "=f"(r) : "f"(x)); return r; }
__device__ __forceinline__ float rcpa(float x){ float r; asm("rcp.approx.ftz.f32 %0, %1;" : "=f"(r) : "f"(x)); return r; }

// ===================== Kernel 1: wide tail gather (R11 verbatim) =====================
__global__ __launch_bounds__(GTH)
void gather_kernel(const float* __restrict__ x)
{
    __shared__ unsigned int stage[TCAP * GTH];
    __shared__ unsigned int wsum[GWARPS];
    __shared__ int s_ov;

    const int tid  = threadIdx.x;
    const int lane = tid & 31;
    const int wid  = tid >> 5;
    const int row  = blockIdx.x >> 4;
    const int chk  = blockIdx.x & (CHUNKS - 1);
    const float4* xr = (const float4*)(x + (size_t)row * NPERROW) + (size_t)chk * V4C;

    if (tid == 0) s_ov = 0;
    __syncthreads();

    unsigned int cnt = 0;
    #pragma unroll
    for (int it = 0; it < V4T / 8; it++) {
        float4 v[8];
        #pragma unroll
        for (int s = 0; s < 8; s++)
            v[s] = xr[tid + (it * 8 + s) * GTH];

        #pragma unroll
        for (int s = 0; s < 8; s++) {
            if (fabsf(v[s].x) > 2.0f) { if (cnt < TCAP) stage[cnt * GTH + tid] = f2k(v[s].x); cnt++; }
            if (fabsf(v[s].y) > 2.0f) { if (cnt < TCAP) stage[cnt * GTH + tid] = f2k(v[s].y); cnt++; }
            if (fabsf(v[s].z) > 2.0f) { if (cnt < TCAP) stage[cnt * GTH + tid] = f2k(v[s].z); cnt++; }
            if (fabsf(v[s].w) > 2.0f) { if (cnt < TCAP) stage[cnt * GTH + tid] = f2k(v[s].w); cnt++; }
        }
    }
    if (cnt > TCAP) s_ov = 1;   // benign race; ordered by barriers below

    unsigned int inc = cnt;
    #pragma unroll
    for (int o = 1; o < 32; o <<= 1) {
        unsigned int t = __shfl_up_sync(FULLM, inc, o);
        if (lane >= o) inc += t;
    }
    if (lane == 31) wsum[wid] = inc;
    __syncthreads();
    if (tid < GWARPS) {
        unsigned int w = wsum[tid];
        #pragma unroll
        for (int o = 1; o < GWARPS; o <<= 1) {
            unsigned int t = __shfl_up_sync(0xFFu, w, o);
            if (tid >= o) w += t;
        }
        wsum[tid] = w;
    }
    __syncthreads();

    unsigned int pre   = (wid ? wsum[wid - 1] : 0u) + inc - cnt;
    unsigned int total = wsum[GWARPS - 1];
    int ov = s_ov || (total > CSEG);

    if (!ov) {
        unsigned int* dst = &g_buf[row][chk * CSEG + pre];
        for (unsigned int j = 0; j < cnt; j++) dst[j] = stage[j * GTH + tid];
    }
    if (tid == 0) g_ccnt[row][chk] = ov ? 0xFFFFFFFFu : total;
}

// ===================== Kernel 2: per-row short-path select =====================
extern __shared__ unsigned int smem_u[];

// block scan over h[0..nbins) (nbins <= 4096), locate ranks lr0 (and lr1 if != NORANK).
// All threads call. Ends with a barrier; outputs valid after return.
__device__ void scanloc(unsigned int* h, int nbins,
                        unsigned int lr0, unsigned int lr1,
                        unsigned int* out_bin0, unsigned int* out_pre0,
                        unsigned int* out_bin1, unsigned int* out_pre1,
                        unsigned int* wsum, int tid, int lane, int wid)
{
    const int bpt = (nbins + 1023) >> 10;   // 1, 2, or 4
    unsigned int c[4] = {0u, 0u, 0u, 0u};
    unsigned int s = 0;
    #pragma unroll 4
    for (int j = 0; j < bpt; j++) {
        int b = tid * bpt + j;
        if (b < nbins) { c[j] = h[b]; s += c[j]; }
    }
    unsigned int inc = s;
    #pragma unroll
    for (int o = 1; o < 32; o <<= 1) {
        unsigned int t = __shfl_up_sync(FULLM, inc, o);
        if (lane >= o) inc += t;
    }
    if (lane == 31) wsum[wid] = inc;
    __syncthreads();
    if (tid < 32) {
        unsigned int w = wsum[tid];
        #pragma unroll
        for (int o = 1; o < 32; o <<= 1) {
            unsigned int t = __shfl_up_sync(FULLM, w, o);
            if (lane >= o) w += t;
        }
        wsum[tid] = w;
    }
    __syncthreads();
    unsigned int run = (wid ? wsum[wid - 1] : 0u) + inc - s;
    #pragma unroll 4
    for (int j = 0; j < bpt; j++) {
        unsigned int cc = c[j];
        unsigned int b = (unsigned int)(tid * bpt + j);
        if (run <= lr0 && lr0 < run + cc) { *out_bin0 = b; *out_pre0 = run; }
        if (lr1 != NORANK && run <= lr1 && lr1 < run + cc) { *out_bin1 = b; *out_pre1 = run; }
        run += cc;
    }
    __syncthreads();
}

__global__ __launch_bounds__(STH, 1)
void select_kernel(const float* __restrict__ x)
{
    unsigned int* mix   = smem_u;            // MCAP
    unsigned int* h     = mix + MCAP;        // 8192 (hists; reused per phase)
    unsigned int* candL = h + 8192;          // CCAPS (low rel keys)
    unsigned int* candH = candL + CCAPS;     // CCAPS (high rel keys)

    __shared__ unsigned int wsum[32];
    __shared__ unsigned int cpre[CHUNKS + 1];
    __shared__ unsigned int s_M, s_Mlow, s_cl, s_ch;
    __shared__ int          s_mode;
    __shared__ unsigned int binq[4], preq[4], keyq[4];
    __shared__ unsigned int tb[2], tp[2];                 // scratch for refinements
    __shared__ unsigned int bin1[4], pre1[4], bin2[4], pre2[4];  // fallback

    const int tid  = threadIdx.x;
    const int lane = tid & 31;
    const int wid  = tid >> 5;
    const int row  = blockIdx.x;
    const float4* xr = (const float4*)(x + (size_t)row * NPERROW);

    if (tid == 0) {
        unsigned int t = 0; int bad = 0;
        #pragma unroll
        for (int c = 0; c < CHUNKS; c++) {
            unsigned int cc = g_ccnt[row][c];
            if (cc > CSEG) { bad = 1; cc = 0; }
            cpre[c] = t;
            t += cc;
        }
        cpre[CHUNKS] = t;
        s_M = t;
        s_mode = bad ? 1 : 0;
        s_Mlow = 0u; s_cl = 0u; s_ch = 0u;
    }
    __syncthreads();

    const unsigned int M = s_M;
    if (s_mode == 0) {
        unsigned int ml = 0;
        #pragma unroll
        for (int c = 0; c < CHUNKS; c++) {
            unsigned int cnt = cpre[c + 1] - cpre[c];   // <= 1024 = STH
            if ((unsigned int)tid < cnt) {
                unsigned int k = g_buf[row][c * CSEG + tid];
                mix[cpre[c] + tid] = k;
                ml += (k < 0x80000000u);
            }
        }
        #pragma unroll
        for (int o = 16; o > 0; o >>= 1) ml += __shfl_down_sync(FULLM, ml, o);
        if (lane == 0) atomicAdd(&s_Mlow, ml);
    }
    __syncthreads();

    const unsigned int Mlow  = s_Mlow;
    const unsigned int Mhigh = M - Mlow;
    if (s_mode == 0 && (Mlow < 2623u || Mhigh < 2623u)) { if (tid == 0) s_mode = 1; }
    __syncthreads();

    // per-side ranks: low keys are globally smallest; high keys globally largest.
    unsigned int R[4];
    R[0] = 2621u; R[1] = 2622u;
    R[2] = Mhigh - 2623u; R[3] = Mhigh - 2622u;   // only used in mode 0

    if (s_mode == 0) {
        // ---- one pass: both 4096-bin side histograms ----
        for (int j = tid; j < 8192; j += STH) h[j] = 0u;
        __syncthreads();
        for (unsigned int i = tid; i < M; i += STH) {
            unsigned int k = mix[i];
            if (k < 0x80000000u) atomicAdd(&h[k >> 18], 1u);                          // low rel = k
            else                 atomicAdd(&h[4096 + ((k - 0xC0000000u) >> 18)], 1u); // high rel
        }
        __syncthreads();
        scanloc(h,        4096, R[0], R[1], &binq[0], &preq[0], &binq[1], &preq[1], wsum, tid, lane, wid);
        scanloc(h + 4096, 4096, R[2], R[3], &binq[2], &preq[2], &binq[3], &preq[3], wsum, tid, lane, wid);

        // ---- extract candidates in located bin ranges ----
        for (unsigned int i = tid; i < M; i += STH) {
            unsigned int k = mix[i];
            if (k < 0x80000000u) {
                unsigned int b = k >> 18;
                if (b >= binq[0] && b <= binq[1]) {
                    unsigned int p = atomicAdd(&s_cl, 1u);
                    if (p < CCAPS) candL[p] = k;
                }
            } else {
                unsigned int rel = k - 0xC0000000u;
                unsigned int b = rel >> 18;
                if (b >= binq[2] && b <= binq[3]) {
                    unsigned int p = atomicAdd(&s_ch, 1u);
                    if (p < CCAPS) candH[p] = rel;
                }
            }
        }
        __syncthreads();
        if (s_cl > (unsigned int)CCAPS || s_ch > (unsigned int)CCAPS) { if (tid == 0) s_mode = 1; }
        __syncthreads();
    }

    if (s_mode == 0) {
        // ---- 4 tiny refinements over <= CCAPS candidates each ----
        const unsigned int ncl = s_cl, nch = s_ch;
        for (int q = 0; q < 4; q++) {
            unsigned int* cand = (q < 2) ? candL : candH;
            const unsigned int n  = (q < 2) ? ncl : nch;
            const unsigned int b  = binq[q];
            unsigned int lr = R[q] - preq[q];

            for (int j = tid; j < 1024; j += STH) h[j] = 0u;
            __syncthreads();
            for (unsigned int i = tid; i < n; i += STH) {
                unsigned int rel = cand[i];
                if ((rel >> 18) == b) atomicAdd(&h[(rel >> 8) & 1023u], 1u);
            }
            __syncthreads();
            scanloc(h, 1024, lr, NORANK, &tb[0], &tp[0], &tb[1], &tp[1], wsum, tid, lane, wid);
            const unsigned int s1 = tb[0];
            lr -= tp[0];
            const unsigned int t18 = (b << 10) | s1;

            for (int j = tid; j < 256; j += STH) h[j] = 0u;
            __syncthreads();
            for (unsigned int i = tid; i < n; i += STH) {
                unsigned int rel = cand[i];
                if ((rel >> 8) == t18) atomicAdd(&h[rel & 255u], 1u);
            }
            __syncthreads();
            scanloc(h, 256, lr, NORANK, &tb[0], &tp[0], &tb[1], &tp[1], wsum, tid, lane, wid);
            if (tid == 0)
                keyq[q] = ((b << 18) | (s1 << 8) | tb[0]) + ((q < 2) ? 0u : 0xC0000000u);
            __syncthreads();
        }
    } else {
        // ---- exact full-row fallback: 11/11/10-bit radix, 4 ranks in banks ----
        R[0] = 2621u; R[1] = 2622u; R[2] = 259521u; R[3] = 259522u;

        // pass 1: bits [21,32), 2048 bins
        for (int j = tid; j < 2048; j += STH) h[j] = 0u;
        __syncthreads();
        for (int i = tid; i < NV4; i += STH) {
            float4 v = xr[i];
            atomicAdd(&h[f2k(v.x) >> 21], 1u);
            atomicAdd(&h[f2k(v.y) >> 21], 1u);
            atomicAdd(&h[f2k(v.z) >> 21], 1u);
            atomicAdd(&h[f2k(v.w) >> 21], 1u);
        }
        __syncthreads();
        scanloc(h, 2048, R[0], R[1], &bin1[0], &pre1[0], &bin1[1], &pre1[1], wsum, tid, lane, wid);
        scanloc(h, 2048, R[2], R[3], &bin1[2], &pre1[2], &bin1[3], &pre1[3], wsum, tid, lane, wid);

        // pass 2: bits [10,21), 4 banks x 2048
        for (int j = tid; j < 8192; j += STH) h[j] = 0u;
        __syncthreads();
        {
            const unsigned int b0 = bin1[0], b1 = bin1[1], b2 = bin1[2], b3 = bin1[3];
            for (int i = tid; i < NV4; i += STH) {
                float4 v = xr[i];
                unsigned int ks[4] = {f2k(v.x), f2k(v.y), f2k(v.z), f2k(v.w)};
                #pragma unroll
                for (int e = 0; e < 4; e++) {
                    unsigned int t1 = ks[e] >> 21, sub = (ks[e] >> 10) & 2047u;
                    if (t1 == b0) atomicAdd(&h[sub], 1u);
                    if (t1 == b1) atomicAdd(&h[2048 + sub], 1u);
                    if (t1 == b2) atomicAdd(&h[4096 + sub], 1u);
                    if (t1 == b3) atomicAdd(&h[6144 + sub], 1u);
                }
            }
        }
        __syncthreads();
        for (int q = 0; q < 4; q++)
            scanloc(h + q * 2048, 2048, R[q] - pre1[q], NORANK,
                    &bin2[q], &pre2[q], &tb[1], &tp[1], wsum, tid, lane, wid);

        // pass 3: bits [0,10), 4 banks x 1024
        for (int j = tid; j < 4096; j += STH) h[j] = 0u;
        __syncthreads();
        {
            const unsigned int t0 = (bin1[0] << 11) | bin2[0];
            const unsigned int t1 = (bin1[1] << 11) | bin2[1];
            const unsigned int t2 = (bin1[2] << 11) | bin2[2];
            const unsigned int t3 = (bin1[3] << 11) | bin2[3];
            for (int i = tid; i < NV4; i += STH) {
                float4 v = xr[i];
                unsigned int ks[4] = {f2k(v.x), f2k(v.y), f2k(v.z), f2k(v.w)};
                #pragma unroll
                for (int e = 0; e < 4; e++) {
                    unsigned int tt = ks[e] >> 10, sub = ks[e] & 1023u;
                    if (tt == t0) atomicAdd(&h[sub], 1u);
                    if (tt == t1) atomicAdd(&h[1024 + sub], 1u);
                    if (tt == t2) atomicAdd(&h[2048 + sub], 1u);
                    if (tt == t3) atomicAdd(&h[3072 + sub], 1u);
                }
            }
        }
        __syncthreads();
        for (int q = 0; q < 4; q++) {
            scanloc(h + q * 1024, 1024, R[q] - pre1[q] - pre2[q], NORANK,
                    &tb[0], &tp[0], &tb[1], &tp[1], wsum, tid, lane, wid);
            if (tid == 0) keyq[q] = (bin1[q] << 21) | (bin2[q] << 10) | tb[0];
            __syncthreads();
        }
    }

    if (tid == 0) {
        double fracLo = 0.01 * (double)(NPERROW - 1) - 2621.0;
        double fracHi = 0.99 * (double)(NPERROW - 1) - 259521.0;
        double vl0 = (double)k2f(keyq[0]), vl1 = (double)k2f(keyq[1]);
        double vh0 = (double)k2f(keyq[2]), vh1 = (double)k2f(keyq[3]);
        g_q[row][0] = (float)(vl0 + fracLo * (vl1 - vl0));
        g_q[row][1] = (float)(vh0 + fracHi * (vh1 - vh0));
    }
}

// ===================== Kernel 3: streaming gate =====================
__global__ __launch_bounds__(GTH)
void gate_kernel(const float* __restrict__ x, float* __restrict__ out,
                 const float* __restrict__ alpha_p, const float* __restrict__ beta_p)
{
    const int c   = blockIdx.x;
    const int row = c >> 4;            // CHUNKS = 16
    const int chk = c & 15;
    const float4* xr   = (const float4*)(x   + (size_t)row * NPERROW) + (size_t)chk * V4C;
    float4*       outr = (float4*)      (out + (size_t)row * NPERROW) + (size_t)chk * V4C;

    const double i1  = (double)g_q[row][0];
    const double i99 = (double)g_q[row][1];
    const float alpha = alpha_p[0];
    const float beta  = beta_p[0];
    const float th = (float)(i1 + (i99 - i1) * (double)alpha);
    const float mask   = (th > 1e-14f) ? 1.0f : 0.0f;
    const float th_new = th * mask + (1.0f - mask);
    const float scale  = beta / th_new;
    const float t      = th * mask;

    const float L2E = 1.4426950408889634f;
    const float a = scale * L2E;        // exp(-(scale*(|x|-t))) = 2^(-a*|x| + b)
    const float b = scale * t * L2E;

    #pragma unroll 4
    for (int i = threadIdx.x; i < V4C; i += GTH) {
        float4 v = xr[i];
        float4 o;
        o.x = fmaxf(v.x, 0.0f) * rcpa(1.0f + ex2a(fmaf(fabsf(v.x), -a, b)));
        o.y = fmaxf(v.y, 0.0f) * rcpa(1.0f + ex2a(fmaf(fabsf(v.y), -a, b)));
        o.z = fmaxf(v.z, 0.0f) * rcpa(1.0f + ex2a(fmaf(fabsf(v.z), -a, b)));
        o.w = fmaxf(v.w, 0.0f) * rcpa(1.0f + ex2a(fmaf(fabsf(v.w), -a, b)));
        __stcs(&outr[i], o);
    }
}

extern "C" void kernel_launch(void* const* d_in, const int* in_sizes, int n_in,
                              void* d_out, int out_size)
{
    const float* x     = (const float*)d_in[0];
    const float* alpha = (const float*)d_in[1];
    const float* beta  = (const float*)d_in[2];
    float* out = (float*)d_out;

    cudaFuncSetAttribute(select_kernel, cudaFuncAttributeMaxDynamicSharedMemorySize, SEL_SMEM_BYTES);

    gather_kernel<<<NROWS * CHUNKS, GTH>>>(x);
    select_kernel<<<NROWS, STH, SEL_SMEM_BYTES>>>(x);
    gate_kernel<<<NROWS * CHUNKS, GTH>>>(x, out, alpha, beta);
}